// round 15
// baseline (speedup 1.0000x reference)
#include <cuda_runtime.h>
#include <cuda_bf16.h>
#include <math.h>
#include <stdint.h>

// Problem dims
#define LNUM 9
#define BDIM 8
#define SAQ 512
#define SBK 512
#define EDIM 1024
#define HNUM 16
#define DHEAD 64
#define FDIM 4096
#define MROWS (BDIM*SAQ)          // 4096

typedef __nv_bfloat16 bf16;
typedef __nv_bfloat162 bf162;

// ---------------- scratch (device globals) ----------------------------------
__device__ float g_A  [MROWS*EDIM];
__device__ float g_A1 [MROWS*EDIM];
__device__ float g_TMP[MROWS*EDIM];
__device__ float g_S  [(long)BDIM*HNUM*SAQ*SBK];
__device__ float g_PART[1024];

__device__ bf16 g_Ahi [MROWS*EDIM],  g_Alo [MROWS*EDIM];
__device__ bf16 g_A1hi[MROWS*EDIM],  g_A1lo[MROWS*EDIM];
__device__ bf16 g_Dhi [BDIM*SBK*EDIM], g_Dlo [BDIM*SBK*EDIM];
__device__ bf16 g_Qhi [MROWS*EDIM],  g_Qlo [MROWS*EDIM];
__device__ bf16 g_KVhi[(long)LNUM*MROWS*2*EDIM], g_KVlo[(long)LNUM*MROWS*2*EDIM];
__device__ bf16 g_VThi[(long)LNUM*EDIM*MROWS],  g_VTlo[(long)LNUM*EDIM*MROWS];
__device__ bf16 g_Phi [(long)BDIM*HNUM*SAQ*SBK], g_Plo[(long)BDIM*HNUM*SAQ*SBK];
__device__ bf16 g_CThi[MROWS*EDIM],  g_CTlo[MROWS*EDIM];
__device__ bf16 g_MIDhi[(long)MROWS*FDIM], g_MIDlo[(long)MROWS*FDIM];
__device__ bf16 g_IPWhi[LNUM*3*EDIM*EDIM], g_IPWlo[LNUM*3*EDIM*EDIM];
__device__ bf16 g_OWhi [LNUM*EDIM*EDIM],   g_OWlo [LNUM*EDIM*EDIM];
__device__ bf16 g_W1hi [(long)LNUM*FDIM*EDIM], g_W1lo[(long)LNUM*FDIM*EDIM];
__device__ bf16 g_W2hi [(long)LNUM*EDIM*FDIM], g_W2lo[(long)LNUM*EDIM*FDIM];

// ---------------- helpers ----------------------------------------------------
__device__ __forceinline__ void split2(float v, bf16& h, bf16& l) {
    h = __float2bfloat16(v);
    l = __float2bfloat16(v - __bfloat162float(h));
}
__device__ __forceinline__ unsigned pack2h(bf16 a, bf16 b) {
    return (uint32_t)__bfloat16_as_ushort(a) | ((uint32_t)__bfloat16_as_ushort(b) << 16);
}
__device__ __forceinline__ void split4(float4 v, uint2& H, uint2& L) {
    bf16 h0,l0,h1,l1,h2,l2,h3,l3;
    split2(v.x,h0,l0); split2(v.y,h1,l1); split2(v.z,h2,l2); split2(v.w,h3,l3);
    H.x = pack2h(h0,h1); H.y = pack2h(h2,h3);
    L.x = pack2h(l0,l1); L.y = pack2h(l2,l3);
}

__device__ __forceinline__ uint32_t smem_u32(const void* p) {
    uint32_t a;
    asm("{ .reg .u64 t; cvta.to.shared.u64 t, %1; cvt.u32.u64 %0, t; }"
        : "=r"(a) : "l"(p));
    return a;
}

#define CPA16(dst, src) \
    asm volatile("cp.async.cg.shared.global [%0], [%1], 16;" :: "r"(dst), "l"(src))
#define CPA_COMMIT() asm volatile("cp.async.commit_group;" ::: "memory")
#define CPA_WAIT1()  asm volatile("cp.async.wait_group 1;" ::: "memory")
#define CPA_WAIT0()  asm volatile("cp.async.wait_group 0;" ::: "memory")

__device__ __forceinline__ void ldsm4(unsigned* r, uint32_t addr) {
    asm volatile("ldmatrix.sync.aligned.m8n8.x4.shared.b16 {%0,%1,%2,%3}, [%4];"
        : "=r"(r[0]), "=r"(r[1]), "=r"(r[2]), "=r"(r[3]) : "r"(addr));
}

__device__ __forceinline__ void mma16816(float* d, const unsigned* a, const unsigned* b) {
    asm volatile(
        "mma.sync.aligned.m16n8k16.row.col.f32.bf16.bf16.f32 "
        "{%0,%1,%2,%3},{%4,%5,%6,%7},{%8,%9},{%0,%1,%2,%3};"
        : "+f"(d[0]), "+f"(d[1]), "+f"(d[2]), "+f"(d[3])
        : "r"(a[0]), "r"(a[1]), "r"(a[2]), "r"(a[3]), "r"(b[0]), "r"(b[1]));
}

// ---------------- merged prologue splits (3 launches only) -------------------
__global__ void split_weights(
    const float4* __restrict__ ipw, const float4* __restrict__ ow,
    const float4* __restrict__ w1,  const float4* __restrict__ w2,
    uint2* __restrict__ ih, uint2* __restrict__ il,
    uint2* __restrict__ oh, uint2* __restrict__ ol,
    uint2* __restrict__ w1h, uint2* __restrict__ w1l,
    uint2* __restrict__ w2h, uint2* __restrict__ w2l,
    int q0, int q1, int q2, int q3)
{
    int i = blockIdx.x * blockDim.x + threadIdx.x;
    if (i >= q3) return;
    const float4* s; uint2 *H, *L; int j;
    if (i < q0)      { s = ipw; H = ih;  L = il;  j = i; }
    else if (i < q1) { s = ow;  H = oh;  L = ol;  j = i - q0; }
    else if (i < q2) { s = w1;  H = w1h; L = w1l; j = i - q1; }
    else             { s = w2;  H = w2h; L = w2l; j = i - q2; }
    uint2 Hh, Ll;
    split4(s[j], Hh, Ll);
    H[j] = Hh; L[j] = Ll;
}

__global__ void split_f4(const float4* __restrict__ src, uint2* __restrict__ hi,
                         uint2* __restrict__ lo, int n4) {
    int i = blockIdx.x * blockDim.x + threadIdx.x;
    if (i < n4) {
        uint2 H, L;
        split4(src[i], H, L);
        hi[i] = H; lo[i] = L;
    }
}

__global__ void split_copy(const float4* __restrict__ src, uint2* __restrict__ hi,
                           uint2* __restrict__ lo, float4* __restrict__ dst, int n4) {
    int i = blockIdx.x * blockDim.x + threadIdx.x;
    if (i < n4) {
        float4 v = src[i];
        uint2 H, L;
        split4(v, H, L);
        hi[i] = H; lo[i] = L; dst[i] = v;
    }
}

// V-half of KV [4096][2048] (cols 1024..2047) bf16 -> VT [1024][4096] bf16
__global__ void transpose_v(const bf16* __restrict__ KVhi, const bf16* __restrict__ KVlo,
                            bf16* __restrict__ VThi, bf16* __restrict__ VTlo) {
    __shared__ bf16 th[32][33];
    __shared__ bf16 tl[32][33];
    long kvb = (long)blockIdx.z * MROWS * 2 * EDIM;
    long vtb = (long)blockIdx.z * EDIM * MROWS;
    int bx = blockIdx.x * 32, by = blockIdx.y * 32;
    int tx = threadIdx.x, ty = threadIdx.y;
#pragma unroll
    for (int i = 0; i < 4; i++) {
        long o = kvb + (long)(by + ty + i*8) * (2*EDIM) + EDIM + bx + tx;
        th[ty + i*8][tx] = KVhi[o];
        tl[ty + i*8][tx] = KVlo[o];
    }
    __syncthreads();
#pragma unroll
    for (int i = 0; i < 4; i++) {
        long o = vtb + (long)(bx + ty + i*8) * MROWS + by + tx;
        VThi[o] = th[tx][ty + i*8];
        VTlo[o] = tl[tx][ty + i*8];
    }
}

// ---------------- bf16x3 warp-MMA GEMM (TN), cp.async + ldmatrix -------------
// Quad-burst inner loop; all loop-invariant addresses hoisted:
// loader uses precomputed (src ptr, smem dst) pairs; ldsm uses precomputed
// k0-independent byte offsets. Per-acc add order HH, HL, LH (bit-identical).
template<int BN>
__global__ void __launch_bounds__(256, 2) gemm_bf3(
    const bf16* __restrict__ Ahi_g, const bf16* __restrict__ Alo_g,
    const bf16* __restrict__ Bhi_g, const bf16* __restrict__ Blo_g,
    const float* __restrict__ bias,
    float* __restrict__ Cf, bf16* __restrict__ Chi, bf16* __restrict__ Clo,
    int K, int lda, int ldb, int ldc,
    long sAb, long sAh, long sBb, long sBh, long sCb, long sCh, int nH,
    long sBias,
    float alpha, int mode, int relu)
{
    constexpr int KS  = 40;
    constexpr int AST = 128 * KS;
    constexpr int BST = BN * KS;
    constexpr int STG = 2 * AST + 2 * BST;
    constexpr int NT  = BN / 16;
    constexpr int NITER = (256 + 2 * BN) * 4 / 256;   // 8 (BN=128) or 6 (BN=64)

    extern __shared__ bf16 sm[];
    uint32_t smb = smem_u32(sm);

    int bz = blockIdx.z;
    int bb = bz / nH, hh = bz % nH;
    const bf16* Ah = Ahi_g + bb * sAb + hh * sAh;
    const bf16* Al = Alo_g + bb * sAb + hh * sAh;
    const bf16* Bh = Bhi_g + bb * sBb + hh * sBh;
    const bf16* Bl = Blo_g + bb * sBb + hh * sBh;
    const float* biasp = bias ? bias + bb * sBias : (const float*)0;
    long cbase = bb * sCb + hh * sCh;

    int bm = blockIdx.y * 128, bn = blockIdx.x * BN;
    int tid = threadIdx.x;
    int wid = tid >> 5, lane = tid & 31;
    int wm = wid & 3, wn = wid >> 2;
    int mb = wm * 32, nb = wn * (BN / 2);
    int lr = lane >> 2, lc = (lane & 3) * 2;

    int a_ro = lane & 15;
    int a_co = (lane >> 4) << 3;
    int b_ro = (lane & 7) | (((lane >> 4) & 1) << 3);
    int b_co = ((lane >> 3) & 1) << 3;

    // ---- precompute loader (src, dst) pairs (kt = 0) ----
    const bf16* lsrc[NITER];
    uint32_t ldst[NITER];
#pragma unroll
    for (int it = 0; it < NITER; it++) {
        int i = tid + it * 256;
        int row = i >> 2, seg = (i & 3) << 3;
        const bf16* src; uint32_t toff; int r;
        if (row < 256) {
            r = row & 127;
            src  = (row < 128 ? Ah : Al) + (long)(bm + r) * lda + seg;
            toff = (row < 128) ? 0u : (uint32_t)AST;
        } else {
            int rb = row - 256;
            r = rb & (BN - 1);
            src  = (rb < BN ? Bh : Bl) + (long)(bn + r) * ldb + seg;
            toff = (rb < BN) ? (uint32_t)(2 * AST) : (uint32_t)(2 * AST + BST);
        }
        lsrc[it] = src;
        ldst[it] = (toff + (uint32_t)(r * KS + seg)) * 2u;
    }

    // ---- precompute ldsm byte offsets (k0-independent) ----
    uint32_t aOff[2];
#pragma unroll
    for (int mt = 0; mt < 2; mt++)
        aOff[mt] = (uint32_t)(((mb + mt * 16 + a_ro) * KS + a_co) * 2);
    uint32_t bOff = (uint32_t)(((nb + b_ro) * KS + b_co) * 2);   // + nt*8*KS*2

    float acc[2][NT][4];
#pragma unroll
    for (int i = 0; i < 2; i++)
#pragma unroll
        for (int j = 0; j < NT; j++)
#pragma unroll
            for (int q = 0; q < 4; q++) acc[i][j][q] = 0.f;

    auto load_stage = [&](int s, int kt) {
        uint32_t sb = smb + (uint32_t)s * (STG * 2);
#pragma unroll
        for (int it = 0; it < NITER; it++)
            CPA16(sb + ldst[it], lsrc[it] + kt);
        CPA_COMMIT();
    };

    const int NC = K >> 5;
    load_stage(0, 0);

    for (int c = 0; c < NC; c++) {
        int s = c & 1;
        if (c + 1 < NC) { load_stage(s ^ 1, (c + 1) << 5); CPA_WAIT1(); }
        else            { CPA_WAIT0(); }
        __syncthreads();

        uint32_t sbase = smb + (uint32_t)(s * STG) * 2u;
        uint32_t uAh = sbase;
        uint32_t uAl = sbase + (uint32_t)AST * 2u;
        uint32_t uBh = sbase + (uint32_t)(2 * AST) * 2u;
        uint32_t uBl = uBh + (uint32_t)BST * 2u;

#pragma unroll
        for (int ks = 0; ks < 2; ks++) {
            uint32_t k0b = (uint32_t)(ks * 16 * 2);
            unsigned aH[2][4], aL[2][4];
#pragma unroll
            for (int mt = 0; mt < 2; mt++) {
                ldsm4(aH[mt], uAh + aOff[mt] + k0b);
                ldsm4(aL[mt], uAl + aOff[mt] + k0b);
            }
#pragma unroll
            for (int nt = 0; nt < NT; nt += 4) {
                unsigned bH[8], bL[8];
                uint32_t bo0 = bOff + (uint32_t)(nt * 8 * KS * 2) + k0b;
                uint32_t bo1 = bo0 + (uint32_t)(16 * KS * 2);
                ldsm4(bH,     uBh + bo0);
                ldsm4(bH + 4, uBh + bo1);
                ldsm4(bL,     uBl + bo0);
                ldsm4(bL + 4, uBl + bo1);
#pragma unroll
                for (int mt = 0; mt < 2; mt++)
#pragma unroll
                    for (int q = 0; q < 4; q++)
                        mma16816(acc[mt][nt + q], aH[mt], bH + 2 * q);
#pragma unroll
                for (int mt = 0; mt < 2; mt++)
#pragma unroll
                    for (int q = 0; q < 4; q++)
                        mma16816(acc[mt][nt + q], aH[mt], bL + 2 * q);
#pragma unroll
                for (int mt = 0; mt < 2; mt++)
#pragma unroll
                    for (int q = 0; q < 4; q++)
                        mma16816(acc[mt][nt + q], aL[mt], bH + 2 * q);
            }
        }
        __syncthreads();
    }

#pragma unroll
    for (int mt = 0; mt < 2; mt++) {
#pragma unroll
        for (int nt = 0; nt < NT; nt++) {
            int gm = bm + mb + mt * 16 + lr;
            int gn = bn + nb + nt * 8 + lc;
            float v0 = acc[mt][nt][0] * alpha;
            float v1 = acc[mt][nt][1] * alpha;
            float v2 = acc[mt][nt][2] * alpha;
            float v3 = acc[mt][nt][3] * alpha;
            if (biasp) {
                float c0 = biasp[gn], c1 = biasp[gn + 1];
                v0 += c0; v1 += c1; v2 += c0; v3 += c1;
            }
            if (relu) {
                v0 = fmaxf(v0, 0.f); v1 = fmaxf(v1, 0.f);
                v2 = fmaxf(v2, 0.f); v3 = fmaxf(v3, 0.f);
            }
            long o0 = cbase + (long)gm * ldc + gn;
            long o1 = cbase + (long)(gm + 8) * ldc + gn;
            if (mode == 0) {
                float2 r0; r0.x = v0; r0.y = v1;
                float2 r1; r1.x = v2; r1.y = v3;
                *(float2*)(Cf + o0) = r0;
                *(float2*)(Cf + o1) = r1;
            } else {
                bf16 h0, l0, h1, l1;
                split2(v0, h0, l0); split2(v1, h1, l1);
                *(bf162*)(Chi + o0) = __halves2bfloat162(h0, h1);
                *(bf162*)(Clo + o0) = __halves2bfloat162(l0, l1);
                split2(v2, h0, l0); split2(v3, h1, l1);
                *(bf162*)(Chi + o1) = __halves2bfloat162(h0, h1);
                *(bf162*)(Clo + o1) = __halves2bfloat162(l0, l1);
            }
        }
    }
}

// ---------------- softmax: warp per row of 512 -> split bf16 -----------------
__global__ void __launch_bounds__(256) softmax512(
    const float* __restrict__ S, bf16* __restrict__ Phi, bf16* __restrict__ Plo)
{
    int warp = threadIdx.x >> 5, lane = threadIdx.x & 31;
    long row = (long)blockIdx.x * 8 + warp;
    const float4* p = (const float4*)(S + row * 512);
    float4 v[4];
    float mx = -1e30f;
#pragma unroll
    for (int j = 0; j < 4; j++) {
        v[j] = p[j * 32 + lane];
        mx = fmaxf(mx, fmaxf(fmaxf(v[j].x, v[j].y), fmaxf(v[j].z, v[j].w)));
    }
#pragma unroll
    for (int o = 16; o > 0; o >>= 1)
        mx = fmaxf(mx, __shfl_xor_sync(0xffffffffu, mx, o));
    float sum = 0.f;
#pragma unroll
    for (int j = 0; j < 4; j++) {
        v[j].x = expf(v[j].x - mx); v[j].y = expf(v[j].y - mx);
        v[j].z = expf(v[j].z - mx); v[j].w = expf(v[j].w - mx);
        sum += (v[j].x + v[j].y) + (v[j].z + v[j].w);
    }
#pragma unroll
    for (int o = 16; o > 0; o >>= 1)
        sum += __shfl_xor_sync(0xffffffffu, sum, o);
    float inv = 1.f / sum;
    uint2* ph = (uint2*)(Phi + row * 512);
    uint2* pl = (uint2*)(Plo + row * 512);
#pragma unroll
    for (int j = 0; j < 4; j++) {
        float4 sv;
        sv.x = v[j].x * inv; sv.y = v[j].y * inv;
        sv.z = v[j].z * inv; sv.w = v[j].w * inv;
        uint2 H, L;
        split4(sv, H, L);
        ph[j * 32 + lane] = H;
        pl[j * 32 + lane] = L;
    }
}

// ---------------- fused residual + LayerNorm (+ split outputs) --------------
__global__ void __launch_bounds__(256) add_ln(
    const float* __restrict__ X, const float* __restrict__ R,
    const float* __restrict__ g, const float* __restrict__ b,
    float* __restrict__ Y, bf16* __restrict__ Yhi, bf16* __restrict__ Ylo)
{
    long row = blockIdx.x;
    const float4* x = (const float4*)(X + row * EDIM);
    const float4* r = (const float4*)(R + row * EDIM);
    int t = threadIdx.x, warp = t >> 5, lane = t & 31;
    float4 v = x[t], rr = r[t];
    v.x += rr.x; v.y += rr.y; v.z += rr.z; v.w += rr.w;

    __shared__ float ws[8];
    float s = (v.x + v.y) + (v.z + v.w);
#pragma unroll
    for (int o = 16; o > 0; o >>= 1) s += __shfl_xor_sync(0xffffffffu, s, o);
    if (lane == 0) ws[warp] = s;
    __syncthreads();
    float mean = ((ws[0]+ws[1])+(ws[2]+ws[3])+((ws[4]+ws[5])+(ws[6]+ws[7]))) * (1.f/EDIM);

    float dx = v.x - mean, dy = v.y - mean, dz = v.z - mean, dw = v.w - mean;
    float q = dx*dx + dy*dy + dz*dz + dw*dw;
#pragma unroll
    for (int o = 16; o > 0; o >>= 1) q += __shfl_xor_sync(0xffffffffu, q, o);
    __syncthreads();
    if (lane == 0) ws[warp] = q;
    __syncthreads();
    float var = ((ws[0]+ws[1])+(ws[2]+ws[3])+((ws[4]+ws[5])+(ws[6]+ws[7]))) * (1.f/EDIM);
    float inv = rsqrtf(var + 1e-5f);

    const float4* ggp = (const float4*)(g);
    const float4* bbp = (const float4*)(b);
    float4 gv = ggp[t], bv = bbp[t];
    float4 y;
    y.x = dx * inv * gv.x + bv.x;
    y.y = dy * inv * gv.y + bv.y;
    y.z = dz * inv * gv.z + bv.z;
    y.w = dw * inv * gv.w + bv.w;
    ((float4*)(Y + row * EDIM))[t] = y;
    uint2 H, L;
    split4(y, H, L);
    ((uint2*)(Yhi + row * EDIM))[t] = H;
    ((uint2*)(Ylo + row * EDIM))[t] = L;
}

// ---------------- classifier + loss ------------------------------------------
__global__ void classify(const float* __restrict__ Aout, const float* __restrict__ cw,
                         const float* __restrict__ cb, const int* __restrict__ labels,
                         const int* __restrict__ maskA, const int* __restrict__ cand,
                         float* __restrict__ outp, float* __restrict__ part)
{
    int warp = threadIdx.x >> 5, lane = threadIdx.x & 31;
    int row = blockIdx.x * 8 + warp;
    const float* a = Aout + (long)row * EDIM;
    float d0 = 0.f, d1 = 0.f;
    for (int e = lane; e < EDIM; e += 32) {
        float av = a[e];
        d0 = fmaf(av, cw[e], d0);
        d1 = fmaf(av, cw[EDIM + e], d1);
    }
#pragma unroll
    for (int o = 16; o > 0; o >>= 1) {
        d0 += __shfl_down_sync(0xffffffffu, d0, o);
        d1 += __shfl_down_sync(0xffffffffu, d1, o);
    }
    __shared__ float pw[8][2];
    if (lane == 0) {
        float e0 = d0 + cb[0], e1 = d1 + cb[1];
        int lb = labels[row];
        float mx = fmaxf(e0, e1);
        float lse = mx + logf(expf(e0 - mx) + expf(e1 - mx));
        float ce = lse - ((lb == 1) ? e1 : e0);
        float w = (lb == 1) ? 5.0f : 1.0f;
        float valid = (maskA[row] == 1) ? 1.0f : 0.0f;
        pw[warp][0] = ce * w * valid;
        pw[warp][1] = valid;
        int pred1 = (e1 > e0) ? 1 : 0;
        outp[1 + row] = ((cand[row] == 1) && pred1) ? 1.0f : 0.0f;
    }
    __syncthreads();
    if (threadIdx.x == 0) {
        float s0 = 0.f, s1 = 0.f;
#pragma unroll
        for (int i = 0; i < 8; i++) { s0 += pw[i][0]; s1 += pw[i][1]; }
        part[blockIdx.x * 2 + 0] = s0;
        part[blockIdx.x * 2 + 1] = s1;
    }
}

__global__ void finalize(const float* __restrict__ part, float* __restrict__ outp) {
    __shared__ float r0[512], r1[512];
    int t = threadIdx.x;
    r0[t] = part[t * 2 + 0];
    r1[t] = part[t * 2 + 1];
    __syncthreads();
    for (int s = 256; s > 0; s >>= 1) {
        if (t < s) { r0[t] += r0[t+s]; r1[t] += r1[t+s]; }
        __syncthreads();
    }
    if (t == 0) outp[0] = r0[0] / fmaxf(r1[0], 1.0f);
}

// ---------------- host orchestration ----------------------------------------
extern "C" void kernel_launch(void* const* d_in, const int* in_sizes, int n_in,
                              void* d_out, int out_size)
{
    const float* enc   = (const float*)d_in[0];
    const float* dsc   = (const float*)d_in[1];
    const int*   maskA = (const int*)  d_in[2];
    const int*   cand  = (const int*)  d_in[3];
    const int*   labels= (const int*)  d_in[4];
    const float* ipw   = (const float*)d_in[5];
    const float* ipb   = (const float*)d_in[6];
    const float* ow    = (const float*)d_in[7];
    const float* ob    = (const float*)d_in[8];
    const float* g1    = (const float*)d_in[9];
    const float* b1    = (const float*)d_in[10];
    const float* W1    = (const float*)d_in[11];
    const float* bb1   = (const float*)d_in[12];
    const float* W2    = (const float*)d_in[13];
    const float* bb2   = (const float*)d_in[14];
    const float* g2    = (const float*)d_in[15];
    const float* b2    = (const float*)d_in[16];
    const float* cw    = (const float*)d_in[17];
    const float* cb    = (const float*)d_in[18];

    float *A, *A1, *TMP, *S, *PART;
    bf16 *Ahi,*Alo,*A1hi,*A1lo,*Dhi,*Dlo,*Qhi,*Qlo,*KVhi,*KVlo,*VThi,*VTlo;
    bf16 *Phi,*Plo,*CThi,*CTlo,*MIDhi,*MIDlo;
    bf16 *IPWhi,*IPWlo,*OWhi,*OWlo,*W1hi,*W1lo,*W2hi,*W2lo;
    cudaGetSymbolAddress((void**)&A, g_A);     cudaGetSymbolAddress((void**)&A1, g_A1);
    cudaGetSymbolAddress((void**)&TMP, g_TMP);
    cudaGetSymbolAddress((void**)&S, g_S);     cudaGetSymbolAddress((void**)&PART, g_PART);
    cudaGetSymbolAddress((void**)&Ahi, g_Ahi); cudaGetSymbolAddress((void**)&Alo, g_Alo);
    cudaGetSymbolAddress((void**)&A1hi, g_A1hi); cudaGetSymbolAddress((void**)&A1lo, g_A1lo);
    cudaGetSymbolAddress((void**)&Dhi, g_Dhi); cudaGetSymbolAddress((void**)&Dlo, g_Dlo);
    cudaGetSymbolAddress((void**)&Qhi, g_Qhi); cudaGetSymbolAddress((void**)&Qlo, g_Qlo);
    cudaGetSymbolAddress((void**)&KVhi, g_KVhi); cudaGetSymbolAddress((void**)&KVlo, g_KVlo);
    cudaGetSymbolAddress((void**)&VThi, g_VThi); cudaGetSymbolAddress((void**)&VTlo, g_VTlo);
    cudaGetSymbolAddress((void**)&Phi, g_Phi); cudaGetSymbolAddress((void**)&Plo, g_Plo);
    cudaGetSymbolAddress((void**)&CThi, g_CThi); cudaGetSymbolAddress((void**)&CTlo, g_CTlo);
    cudaGetSymbolAddress((void**)&MIDhi, g_MIDhi); cudaGetSymbolAddress((void**)&MIDlo, g_MIDlo);
    cudaGetSymbolAddress((void**)&IPWhi, g_IPWhi); cudaGetSymbolAddress((void**)&IPWlo, g_IPWlo);
    cudaGetSymbolAddress((void**)&OWhi, g_OWhi); cudaGetSymbolAddress((void**)&OWlo, g_OWlo);
    cudaGetSymbolAddress((void**)&W1hi, g_W1hi); cudaGetSymbolAddress((void**)&W1lo, g_W1lo);
    cudaGetSymbolAddress((void**)&W2hi, g_W2hi); cudaGetSymbolAddress((void**)&W2lo, g_W2lo);

    const int SMEM128 = 2 * (2*128*40 + 2*128*40) * 2;   // 81920 B
    const int SMEM64  = 2 * (2*128*40 + 2*64*40)  * 2;   // 61440 B
    static int attr_done = 0;
    if (!attr_done) {
        cudaFuncSetAttribute(gemm_bf3<128>, cudaFuncAttributeMaxDynamicSharedMemorySize, SMEM128);
        cudaFuncSetAttribute(gemm_bf3<64>,  cudaFuncAttributeMaxDynamicSharedMemorySize, SMEM64);
        attr_done = 1;
    }

    // ---- prologue: 3 split launches ----
    int q0 = LNUM*3*EDIM*EDIM/4;
    int q1 = q0 + LNUM*EDIM*EDIM/4;
    int q2 = q1 + LNUM*FDIM*EDIM/4;
    int q3 = q2 + LNUM*EDIM*FDIM/4;
    split_weights<<<(q3+255)/256, 256>>>(
        (const float4*)ipw, (const float4*)ow, (const float4*)W1, (const float4*)W2,
        (uint2*)IPWhi, (uint2*)IPWlo, (uint2*)OWhi, (uint2*)OWlo,
        (uint2*)W1hi, (uint2*)W1lo, (uint2*)W2hi, (uint2*)W2lo, q0, q1, q2, q3);
    split_f4<<<(BDIM*SBK*EDIM/4+255)/256, 256>>>((const float4*)dsc, (uint2*)Dhi, (uint2*)Dlo, BDIM*SBK*EDIM/4);
    split_copy<<<(MROWS*EDIM/4+255)/256, 256>>>((const float4*)enc, (uint2*)Ahi, (uint2*)Alo, (float4*)A, MROWS*EDIM/4);

    const long KVSTRIDE = (long)MROWS * 2 * EDIM;
    const long VTSTRIDE = (long)EDIM * MROWS;

    // ---- hoisted: ALL layers' K|V projections as one dense batched GEMM ----
    {
        dim3 gKVall(2*EDIM/128, MROWS/128, LNUM);
        gemm_bf3<128><<<gKVall, 256, SMEM128>>>(
            Dhi, Dlo, IPWhi + EDIM*EDIM, IPWlo + EDIM*EDIM, ipb + EDIM,
            0, KVhi, KVlo,
            EDIM, EDIM, EDIM, 2*EDIM,
            0, 0,
            (long)3*EDIM*EDIM, 0,
            KVSTRIDE, 0, 1,
            (long)3*EDIM,
            1.0f, 1, 0);
        dim3 gTall(EDIM/32, MROWS/32, LNUM);
        dim3 bT(32, 8, 1);
        transpose_v<<<gTall, bT>>>(KVhi, KVlo, VThi, VTlo);
    }

    const float scaleS = 0.125f;   // 1/sqrt(64)
    dim3 gP (EDIM/128, MROWS/128, 1);
    dim3 gF1(FDIM/128, MROWS/128, 1);
    dim3 gS (SBK/128, SAQ/128, BDIM*HNUM);
    dim3 gC (1, SAQ/128, BDIM*HNUM);

    for (int l = 0; l < LNUM; l++) {
        const bf16 *wqh = IPWhi + (long)l*3*EDIM*EDIM, *wql = IPWlo + (long)l*3*EDIM*EDIM;
        const float *bq = ipb + (long)l*3*EDIM;
        const bf16 *KVl_h = KVhi + l*KVSTRIDE, *KVl_l = KVlo + l*KVSTRIDE;
        const bf16 *VTl_h = VThi + l*VTSTRIDE, *VTl_l = VTlo + l*VTSTRIDE;

        // Q = A @ wq^T + bq
        gemm_bf3<128><<<gP, 256, SMEM128>>>(Ahi, Alo, wqh, wql, bq, 0, Qhi, Qlo,
            EDIM, EDIM, EDIM, EDIM, 0,0,0,0,0,0,1, 0, 1.0f, 1, 0);

        // scores = scale * Q @ K^T   (K = KV cols 0..1023, row stride 2048)
        gemm_bf3<128><<<gS, 256, SMEM128>>>(Qhi, Qlo, KVl_h, KVl_l, 0, S, 0, 0,
            DHEAD, EDIM, 2*EDIM, SBK,
            (long)SAQ*EDIM, DHEAD, (long)SBK*2*EDIM, DHEAD,
            (long)HNUM*SAQ*SBK, (long)SAQ*SBK, HNUM, 0, scaleS, 0, 0);

        softmax512<<<BDIM*HNUM*SAQ/8, 256>>>(S, Phi, Plo);

        // ctx = P @ V  (TN vs VT)
        gemm_bf3<64><<<gC, 256, SMEM64>>>(Phi, Plo, VTl_h, VTl_l, 0, 0, CThi, CTlo,
            SBK, SBK, MROWS, EDIM,
            (long)HNUM*SAQ*SBK, (long)SAQ*SBK,
            (long)SBK, (long)DHEAD*MROWS,
            (long)SAQ*EDIM, DHEAD, HNUM, 0, 1.0f, 1, 0);

        gemm_bf3<128><<<gP, 256, SMEM128>>>(CThi, CTlo, OWhi + (long)l*EDIM*EDIM,
            OWlo + (long)l*EDIM*EDIM, ob + (long)l*EDIM, TMP, 0, 0,
            EDIM, EDIM, EDIM, EDIM, 0,0,0,0,0,0,1, 0, 1.0f, 0, 0);

        add_ln<<<MROWS, 256>>>(A, TMP, g1 + (long)l*EDIM, b1 + (long)l*EDIM,
                               A1, A1hi, A1lo);

        gemm_bf3<128><<<gF1, 256, SMEM128>>>(A1hi, A1lo, W1hi + (long)l*FDIM*EDIM,
            W1lo + (long)l*FDIM*EDIM, bb1 + (long)l*FDIM, 0, MIDhi, MIDlo,
            EDIM, EDIM, EDIM, FDIM, 0,0,0,0,0,0,1, 0, 1.0f, 1, 1);

        gemm_bf3<128><<<gP, 256, SMEM128>>>(MIDhi, MIDlo, W2hi + (long)l*EDIM*FDIM,
            W2lo + (long)l*EDIM*FDIM, bb2 + (long)l*EDIM, TMP, 0, 0,
            FDIM, FDIM, FDIM, EDIM, 0,0,0,0,0,0,1, 0, 1.0f, 0, 0);

        add_ln<<<MROWS, 256>>>(A1, TMP, g2 + (long)l*EDIM, b2 + (long)l*EDIM,
                               A, Ahi, Alo);
    }

    classify<<<MROWS/8, 256>>>(A, cw, cb, labels, maskA, cand, (float*)d_out, PART);
    finalize<<<1, 512>>>(PART, (float*)d_out);
}

// round 16
// speedup vs baseline: 1.0401x; 1.0401x over previous
#include <cuda_runtime.h>
#include <cuda_bf16.h>
#include <math.h>
#include <stdint.h>

// Problem dims
#define LNUM 9
#define BDIM 8
#define SAQ 512
#define SBK 512
#define EDIM 1024
#define HNUM 16
#define DHEAD 64
#define FDIM 4096
#define MROWS (BDIM*SAQ)          // 4096

typedef __nv_bfloat16 bf16;
typedef __nv_bfloat162 bf162;

// ---------------- scratch (device globals) ----------------------------------
__device__ float g_A  [MROWS*EDIM];
__device__ float g_A1 [MROWS*EDIM];
__device__ float g_TMP[MROWS*EDIM];
__device__ float g_S  [(long)BDIM*HNUM*SAQ*SBK];
__device__ float g_PART[1024];

__device__ bf16 g_Ahi [MROWS*EDIM],  g_Alo [MROWS*EDIM];
__device__ bf16 g_A1hi[MROWS*EDIM],  g_A1lo[MROWS*EDIM];
__device__ bf16 g_Dhi [BDIM*SBK*EDIM], g_Dlo [BDIM*SBK*EDIM];
__device__ bf16 g_Qhi [MROWS*EDIM],  g_Qlo [MROWS*EDIM];
__device__ bf16 g_KVhi[(long)LNUM*MROWS*2*EDIM], g_KVlo[(long)LNUM*MROWS*2*EDIM];
__device__ bf16 g_VThi[(long)LNUM*EDIM*MROWS],  g_VTlo[(long)LNUM*EDIM*MROWS];
__device__ bf16 g_Phi [(long)BDIM*HNUM*SAQ*SBK], g_Plo[(long)BDIM*HNUM*SAQ*SBK];
__device__ bf16 g_CThi[MROWS*EDIM],  g_CTlo[MROWS*EDIM];
__device__ bf16 g_MIDhi[(long)MROWS*FDIM], g_MIDlo[(long)MROWS*FDIM];
__device__ bf16 g_IPWhi[LNUM*3*EDIM*EDIM], g_IPWlo[LNUM*3*EDIM*EDIM];
__device__ bf16 g_OWhi [LNUM*EDIM*EDIM],   g_OWlo [LNUM*EDIM*EDIM];
__device__ bf16 g_W1hi [(long)LNUM*FDIM*EDIM], g_W1lo[(long)LNUM*FDIM*EDIM];
__device__ bf16 g_W2hi [(long)LNUM*EDIM*FDIM], g_W2lo[(long)LNUM*EDIM*FDIM];

// ---------------- helpers ----------------------------------------------------
__device__ __forceinline__ void split2(float v, bf16& h, bf16& l) {
    h = __float2bfloat16(v);
    l = __float2bfloat16(v - __bfloat162float(h));
}
__device__ __forceinline__ unsigned pack2h(bf16 a, bf16 b) {
    return (uint32_t)__bfloat16_as_ushort(a) | ((uint32_t)__bfloat16_as_ushort(b) << 16);
}
__device__ __forceinline__ void split4(float4 v, uint2& H, uint2& L) {
    bf16 h0,l0,h1,l1,h2,l2,h3,l3;
    split2(v.x,h0,l0); split2(v.y,h1,l1); split2(v.z,h2,l2); split2(v.w,h3,l3);
    H.x = pack2h(h0,h1); H.y = pack2h(h2,h3);
    L.x = pack2h(l0,l1); L.y = pack2h(l2,l3);
}

__device__ __forceinline__ uint32_t smem_u32(const void* p) {
    uint32_t a;
    asm("{ .reg .u64 t; cvta.to.shared.u64 t, %1; cvt.u32.u64 %0, t; }"
        : "=r"(a) : "l"(p));
    return a;
}

#define CPA16(dst, src) \
    asm volatile("cp.async.cg.shared.global [%0], [%1], 16;" :: "r"(dst), "l"(src))
#define CPA_COMMIT() asm volatile("cp.async.commit_group;" ::: "memory")
#define CPA_WAIT1()  asm volatile("cp.async.wait_group 1;" ::: "memory")
#define CPA_WAIT0()  asm volatile("cp.async.wait_group 0;" ::: "memory")

__device__ __forceinline__ void ldsm4(unsigned* r, uint32_t addr) {
    asm volatile("ldmatrix.sync.aligned.m8n8.x4.shared.b16 {%0,%1,%2,%3}, [%4];"
        : "=r"(r[0]), "=r"(r[1]), "=r"(r[2]), "=r"(r[3]) : "r"(addr));
}

__device__ __forceinline__ void mma16816(float* d, const unsigned* a, const unsigned* b) {
    asm volatile(
        "mma.sync.aligned.m16n8k16.row.col.f32.bf16.bf16.f32 "
        "{%0,%1,%2,%3},{%4,%5,%6,%7},{%8,%9},{%0,%1,%2,%3};"
        : "+f"(d[0]), "+f"(d[1]), "+f"(d[2]), "+f"(d[3])
        : "r"(a[0]), "r"(a[1]), "r"(a[2]), "r"(a[3]), "r"(b[0]), "r"(b[1]));
}

// ---------------- merged prologue splits (3 launches only) -------------------
__global__ void split_weights(
    const float4* __restrict__ ipw, const float4* __restrict__ ow,
    const float4* __restrict__ w1,  const float4* __restrict__ w2,
    uint2* __restrict__ ih, uint2* __restrict__ il,
    uint2* __restrict__ oh, uint2* __restrict__ ol,
    uint2* __restrict__ w1h, uint2* __restrict__ w1l,
    uint2* __restrict__ w2h, uint2* __restrict__ w2l,
    int q0, int q1, int q2, int q3)
{
    int i = blockIdx.x * blockDim.x + threadIdx.x;
    if (i >= q3) return;
    const float4* s; uint2 *H, *L; int j;
    if (i < q0)      { s = ipw; H = ih;  L = il;  j = i; }
    else if (i < q1) { s = ow;  H = oh;  L = ol;  j = i - q0; }
    else if (i < q2) { s = w1;  H = w1h; L = w1l; j = i - q1; }
    else             { s = w2;  H = w2h; L = w2l; j = i - q2; }
    uint2 Hh, Ll;
    split4(s[j], Hh, Ll);
    H[j] = Hh; L[j] = Ll;
}

__global__ void split_f4(const float4* __restrict__ src, uint2* __restrict__ hi,
                         uint2* __restrict__ lo, int n4) {
    int i = blockIdx.x * blockDim.x + threadIdx.x;
    if (i < n4) {
        uint2 H, L;
        split4(src[i], H, L);
        hi[i] = H; lo[i] = L;
    }
}

__global__ void split_copy(const float4* __restrict__ src, uint2* __restrict__ hi,
                           uint2* __restrict__ lo, float4* __restrict__ dst, int n4) {
    int i = blockIdx.x * blockDim.x + threadIdx.x;
    if (i < n4) {
        float4 v = src[i];
        uint2 H, L;
        split4(v, H, L);
        hi[i] = H; lo[i] = L; dst[i] = v;
    }
}

// V-half of KV [4096][2048] (cols 1024..2047) bf16 -> VT [1024][4096] bf16
__global__ void transpose_v(const bf16* __restrict__ KVhi, const bf16* __restrict__ KVlo,
                            bf16* __restrict__ VThi, bf16* __restrict__ VTlo) {
    __shared__ bf16 th[32][33];
    __shared__ bf16 tl[32][33];
    long kvb = (long)blockIdx.z * MROWS * 2 * EDIM;
    long vtb = (long)blockIdx.z * EDIM * MROWS;
    int bx = blockIdx.x * 32, by = blockIdx.y * 32;
    int tx = threadIdx.x, ty = threadIdx.y;
#pragma unroll
    for (int i = 0; i < 4; i++) {
        long o = kvb + (long)(by + ty + i*8) * (2*EDIM) + EDIM + bx + tx;
        th[ty + i*8][tx] = KVhi[o];
        tl[ty + i*8][tx] = KVlo[o];
    }
    __syncthreads();
#pragma unroll
    for (int i = 0; i < 4; i++) {
        long o = vtb + (long)(bx + ty + i*8) * MROWS + by + tx;
        VThi[o] = th[tx][ty + i*8];
        VTlo[o] = tl[tx][ty + i*8];
    }
}

// ---------------- bf16x3 warp-MMA GEMM (TN), cp.async + ldmatrix -------------
// R14 loader (per-stage address recompute — latency filler is free);
// hoisted ldsm byte offsets only (cheap). Per-acc order HH, HL, LH.
template<int BN>
__global__ void __launch_bounds__(256, 2) gemm_bf3(
    const bf16* __restrict__ Ahi_g, const bf16* __restrict__ Alo_g,
    const bf16* __restrict__ Bhi_g, const bf16* __restrict__ Blo_g,
    const float* __restrict__ bias,
    float* __restrict__ Cf, bf16* __restrict__ Chi, bf16* __restrict__ Clo,
    int K, int lda, int ldb, int ldc,
    long sAb, long sAh, long sBb, long sBh, long sCb, long sCh, int nH,
    long sBias,
    float alpha, int mode, int relu)
{
    constexpr int KS  = 40;
    constexpr int AST = 128 * KS;
    constexpr int BST = BN * KS;
    constexpr int STG = 2 * AST + 2 * BST;
    constexpr int NT  = BN / 16;

    extern __shared__ bf16 sm[];
    uint32_t smb = smem_u32(sm);

    int bz = blockIdx.z;
    int bb = bz / nH, hh = bz % nH;
    const bf16* Ah = Ahi_g + bb * sAb + hh * sAh;
    const bf16* Al = Alo_g + bb * sAb + hh * sAh;
    const bf16* Bh = Bhi_g + bb * sBb + hh * sBh;
    const bf16* Bl = Blo_g + bb * sBb + hh * sBh;
    const float* biasp = bias ? bias + bb * sBias : (const float*)0;
    long cbase = bb * sCb + hh * sCh;

    int bm = blockIdx.y * 128, bn = blockIdx.x * BN;
    int tid = threadIdx.x;
    int wid = tid >> 5, lane = tid & 31;
    int wm = wid & 3, wn = wid >> 2;
    int mb = wm * 32, nb = wn * (BN / 2);
    int lr = lane >> 2, lc = (lane & 3) * 2;

    int a_ro = lane & 15;
    int a_co = (lane >> 4) << 3;
    int b_ro = (lane & 7) | (((lane >> 4) & 1) << 3);
    int b_co = ((lane >> 3) & 1) << 3;

    // hoisted ldsm byte offsets (k0-independent, ~3 regs)
    uint32_t aOff[2];
#pragma unroll
    for (int mt = 0; mt < 2; mt++)
        aOff[mt] = (uint32_t)(((mb + mt * 16 + a_ro) * KS + a_co) * 2);
    uint32_t bOff = (uint32_t)(((nb + b_ro) * KS + b_co) * 2);

    float acc[2][NT][4];
#pragma unroll
    for (int i = 0; i < 2; i++)
#pragma unroll
        for (int j = 0; j < NT; j++)
#pragma unroll
            for (int q = 0; q < 4; q++) acc[i][j][q] = 0.f;

    auto load_stage = [&](int s, int kt) {
        uint32_t sb = smb + (uint32_t)s * (STG * 2);
#pragma unroll 4
        for (int i = tid; i < (256 + 2 * BN) * 4; i += 256) {
            int row = i >> 2, seg = (i & 3) << 3;
            const bf16* src; uint32_t toff; int r;
            if (row < 256) {
                r = row & 127;
                src  = (row < 128 ? Ah : Al) + (long)(bm + r) * lda + kt + seg;
                toff = (row < 128) ? 0u : (uint32_t)AST;
            } else {
                int rb = row - 256;
                r = rb & (BN - 1);
                src  = (rb < BN ? Bh : Bl) + (long)(bn + r) * ldb + kt + seg;
                toff = (rb < BN) ? (uint32_t)(2 * AST) : (uint32_t)(2 * AST + BST);
            }
            uint32_t dst = sb + (toff + (uint32_t)(r * KS + seg)) * 2u;
            CPA16(dst, src);
        }
        CPA_COMMIT();
    };

    const int NC = K >> 5;
    load_stage(0, 0);

    for (int c = 0; c < NC; c++) {
        int s = c & 1;
        if (c + 1 < NC) { load_stage(s ^ 1, (c + 1) << 5); CPA_WAIT1(); }
        else            { CPA_WAIT0(); }
        __syncthreads();

        uint32_t sbase = smb + (uint32_t)(s * STG) * 2u;
        uint32_t uAh = sbase;
        uint32_t uAl = sbase + (uint32_t)AST * 2u;
        uint32_t uBh = sbase + (uint32_t)(2 * AST) * 2u;
        uint32_t uBl = uBh + (uint32_t)BST * 2u;

#pragma unroll
        for (int ks = 0; ks < 2; ks++) {
            uint32_t k0b = (uint32_t)(ks * 32);
            unsigned aH[2][4], aL[2][4];
#pragma unroll
            for (int mt = 0; mt < 2; mt++) {
                ldsm4(aH[mt], uAh + aOff[mt] + k0b);
                ldsm4(aL[mt], uAl + aOff[mt] + k0b);
            }
#pragma unroll
            for (int nt = 0; nt < NT; nt += 4) {
                unsigned bH[8], bL[8];
                uint32_t bo0 = bOff + (uint32_t)(nt * 8 * KS * 2) + k0b;
                uint32_t bo1 = bo0 + (uint32_t)(16 * KS * 2);
                ldsm4(bH,     uBh + bo0);
                ldsm4(bH + 4, uBh + bo1);
                ldsm4(bL,     uBl + bo0);
                ldsm4(bL + 4, uBl + bo1);
#pragma unroll
                for (int mt = 0; mt < 2; mt++)
#pragma unroll
                    for (int q = 0; q < 4; q++)
                        mma16816(acc[mt][nt + q], aH[mt], bH + 2 * q);
#pragma unroll
                for (int mt = 0; mt < 2; mt++)
#pragma unroll
                    for (int q = 0; q < 4; q++)
                        mma16816(acc[mt][nt + q], aH[mt], bL + 2 * q);
#pragma unroll
                for (int mt = 0; mt < 2; mt++)
#pragma unroll
                    for (int q = 0; q < 4; q++)
                        mma16816(acc[mt][nt + q], aL[mt], bH + 2 * q);
            }
        }
        __syncthreads();
    }

#pragma unroll
    for (int mt = 0; mt < 2; mt++) {
#pragma unroll
        for (int nt = 0; nt < NT; nt++) {
            int gm = bm + mb + mt * 16 + lr;
            int gn = bn + nb + nt * 8 + lc;
            float v0 = acc[mt][nt][0] * alpha;
            float v1 = acc[mt][nt][1] * alpha;
            float v2 = acc[mt][nt][2] * alpha;
            float v3 = acc[mt][nt][3] * alpha;
            if (biasp) {
                float c0 = biasp[gn], c1 = biasp[gn + 1];
                v0 += c0; v1 += c1; v2 += c0; v3 += c1;
            }
            if (relu) {
                v0 = fmaxf(v0, 0.f); v1 = fmaxf(v1, 0.f);
                v2 = fmaxf(v2, 0.f); v3 = fmaxf(v3, 0.f);
            }
            long o0 = cbase + (long)gm * ldc + gn;
            long o1 = cbase + (long)(gm + 8) * ldc + gn;
            if (mode == 0) {
                float2 r0; r0.x = v0; r0.y = v1;
                float2 r1; r1.x = v2; r1.y = v3;
                *(float2*)(Cf + o0) = r0;
                *(float2*)(Cf + o1) = r1;
            } else {
                bf16 h0, l0, h1, l1;
                split2(v0, h0, l0); split2(v1, h1, l1);
                *(bf162*)(Chi + o0) = __halves2bfloat162(h0, h1);
                *(bf162*)(Clo + o0) = __halves2bfloat162(l0, l1);
                split2(v2, h0, l0); split2(v3, h1, l1);
                *(bf162*)(Chi + o1) = __halves2bfloat162(h0, h1);
                *(bf162*)(Clo + o1) = __halves2bfloat162(l0, l1);
            }
        }
    }
}

// ---------------- softmax: warp per row of 512 -> split bf16 -----------------
__global__ void __launch_bounds__(256) softmax512(
    const float* __restrict__ S, bf16* __restrict__ Phi, bf16* __restrict__ Plo)
{
    int warp = threadIdx.x >> 5, lane = threadIdx.x & 31;
    long row = (long)blockIdx.x * 8 + warp;
    const float4* p = (const float4*)(S + row * 512);
    float4 v[4];
    float mx = -1e30f;
#pragma unroll
    for (int j = 0; j < 4; j++) {
        v[j] = p[j * 32 + lane];
        mx = fmaxf(mx, fmaxf(fmaxf(v[j].x, v[j].y), fmaxf(v[j].z, v[j].w)));
    }
#pragma unroll
    for (int o = 16; o > 0; o >>= 1)
        mx = fmaxf(mx, __shfl_xor_sync(0xffffffffu, mx, o));
    float sum = 0.f;
#pragma unroll
    for (int j = 0; j < 4; j++) {
        v[j].x = expf(v[j].x - mx); v[j].y = expf(v[j].y - mx);
        v[j].z = expf(v[j].z - mx); v[j].w = expf(v[j].w - mx);
        sum += (v[j].x + v[j].y) + (v[j].z + v[j].w);
    }
#pragma unroll
    for (int o = 16; o > 0; o >>= 1)
        sum += __shfl_xor_sync(0xffffffffu, sum, o);
    float inv = 1.f / sum;
    uint2* ph = (uint2*)(Phi + row * 512);
    uint2* pl = (uint2*)(Plo + row * 512);
#pragma unroll
    for (int j = 0; j < 4; j++) {
        float4 sv;
        sv.x = v[j].x * inv; sv.y = v[j].y * inv;
        sv.z = v[j].z * inv; sv.w = v[j].w * inv;
        uint2 H, L;
        split4(sv, H, L);
        ph[j * 32 + lane] = H;
        pl[j * 32 + lane] = L;
    }
}

// ---------------- fused residual + LayerNorm (+ split outputs) --------------
__global__ void __launch_bounds__(256) add_ln(
    const float* __restrict__ X, const float* __restrict__ R,
    const float* __restrict__ g, const float* __restrict__ b,
    float* __restrict__ Y, bf16* __restrict__ Yhi, bf16* __restrict__ Ylo)
{
    long row = blockIdx.x;
    const float4* x = (const float4*)(X + row * EDIM);
    const float4* r = (const float4*)(R + row * EDIM);
    int t = threadIdx.x, warp = t >> 5, lane = t & 31;
    float4 v = x[t], rr = r[t];
    v.x += rr.x; v.y += rr.y; v.z += rr.z; v.w += rr.w;

    __shared__ float ws[8];
    float s = (v.x + v.y) + (v.z + v.w);
#pragma unroll
    for (int o = 16; o > 0; o >>= 1) s += __shfl_xor_sync(0xffffffffu, s, o);
    if (lane == 0) ws[warp] = s;
    __syncthreads();
    float mean = ((ws[0]+ws[1])+(ws[2]+ws[3])+((ws[4]+ws[5])+(ws[6]+ws[7]))) * (1.f/EDIM);

    float dx = v.x - mean, dy = v.y - mean, dz = v.z - mean, dw = v.w - mean;
    float q = dx*dx + dy*dy + dz*dz + dw*dw;
#pragma unroll
    for (int o = 16; o > 0; o >>= 1) q += __shfl_xor_sync(0xffffffffu, q, o);
    __syncthreads();
    if (lane == 0) ws[warp] = q;
    __syncthreads();
    float var = ((ws[0]+ws[1])+(ws[2]+ws[3])+((ws[4]+ws[5])+(ws[6]+ws[7]))) * (1.f/EDIM);
    float inv = rsqrtf(var + 1e-5f);

    const float4* ggp = (const float4*)(g);
    const float4* bbp = (const float4*)(b);
    float4 gv = ggp[t], bv = bbp[t];
    float4 y;
    y.x = dx * inv * gv.x + bv.x;
    y.y = dy * inv * gv.y + bv.y;
    y.z = dz * inv * gv.z + bv.z;
    y.w = dw * inv * gv.w + bv.w;
    ((float4*)(Y + row * EDIM))[t] = y;
    uint2 H, L;
    split4(y, H, L);
    ((uint2*)(Yhi + row * EDIM))[t] = H;
    ((uint2*)(Ylo + row * EDIM))[t] = L;
}

// ---------------- classifier + loss ------------------------------------------
__global__ void classify(const float* __restrict__ Aout, const float* __restrict__ cw,
                         const float* __restrict__ cb, const int* __restrict__ labels,
                         const int* __restrict__ maskA, const int* __restrict__ cand,
                         float* __restrict__ outp, float* __restrict__ part)
{
    int warp = threadIdx.x >> 5, lane = threadIdx.x & 31;
    int row = blockIdx.x * 8 + warp;
    const float* a = Aout + (long)row * EDIM;
    float d0 = 0.f, d1 = 0.f;
    for (int e = lane; e < EDIM; e += 32) {
        float av = a[e];
        d0 = fmaf(av, cw[e], d0);
        d1 = fmaf(av, cw[EDIM + e], d1);
    }
#pragma unroll
    for (int o = 16; o > 0; o >>= 1) {
        d0 += __shfl_down_sync(0xffffffffu, d0, o);
        d1 += __shfl_down_sync(0xffffffffu, d1, o);
    }
    __shared__ float pw[8][2];
    if (lane == 0) {
        float e0 = d0 + cb[0], e1 = d1 + cb[1];
        int lb = labels[row];
        float mx = fmaxf(e0, e1);
        float lse = mx + logf(expf(e0 - mx) + expf(e1 - mx));
        float ce = lse - ((lb == 1) ? e1 : e0);
        float w = (lb == 1) ? 5.0f : 1.0f;
        float valid = (maskA[row] == 1) ? 1.0f : 0.0f;
        pw[warp][0] = ce * w * valid;
        pw[warp][1] = valid;
        int pred1 = (e1 > e0) ? 1 : 0;
        outp[1 + row] = ((cand[row] == 1) && pred1) ? 1.0f : 0.0f;
    }
    __syncthreads();
    if (threadIdx.x == 0) {
        float s0 = 0.f, s1 = 0.f;
#pragma unroll
        for (int i = 0; i < 8; i++) { s0 += pw[i][0]; s1 += pw[i][1]; }
        part[blockIdx.x * 2 + 0] = s0;
        part[blockIdx.x * 2 + 1] = s1;
    }
}

__global__ void finalize(const float* __restrict__ part, float* __restrict__ outp) {
    __shared__ float r0[512], r1[512];
    int t = threadIdx.x;
    r0[t] = part[t * 2 + 0];
    r1[t] = part[t * 2 + 1];
    __syncthreads();
    for (int s = 256; s > 0; s >>= 1) {
        if (t < s) { r0[t] += r0[t+s]; r1[t] += r1[t+s]; }
        __syncthreads();
    }
    if (t == 0) outp[0] = r0[0] / fmaxf(r1[0], 1.0f);
}

// ---------------- host orchestration ----------------------------------------
extern "C" void kernel_launch(void* const* d_in, const int* in_sizes, int n_in,
                              void* d_out, int out_size)
{
    const float* enc   = (const float*)d_in[0];
    const float* dsc   = (const float*)d_in[1];
    const int*   maskA = (const int*)  d_in[2];
    const int*   cand  = (const int*)  d_in[3];
    const int*   labels= (const int*)  d_in[4];
    const float* ipw   = (const float*)d_in[5];
    const float* ipb   = (const float*)d_in[6];
    const float* ow    = (const float*)d_in[7];
    const float* ob    = (const float*)d_in[8];
    const float* g1    = (const float*)d_in[9];
    const float* b1    = (const float*)d_in[10];
    const float* W1    = (const float*)d_in[11];
    const float* bb1   = (const float*)d_in[12];
    const float* W2    = (const float*)d_in[13];
    const float* bb2   = (const float*)d_in[14];
    const float* g2    = (const float*)d_in[15];
    const float* b2    = (const float*)d_in[16];
    const float* cw    = (const float*)d_in[17];
    const float* cb    = (const float*)d_in[18];

    float *A, *A1, *TMP, *S, *PART;
    bf16 *Ahi,*Alo,*A1hi,*A1lo,*Dhi,*Dlo,*Qhi,*Qlo,*KVhi,*KVlo,*VThi,*VTlo;
    bf16 *Phi,*Plo,*CThi,*CTlo,*MIDhi,*MIDlo;
    bf16 *IPWhi,*IPWlo,*OWhi,*OWlo,*W1hi,*W1lo,*W2hi,*W2lo;
    cudaGetSymbolAddress((void**)&A, g_A);     cudaGetSymbolAddress((void**)&A1, g_A1);
    cudaGetSymbolAddress((void**)&TMP, g_TMP);
    cudaGetSymbolAddress((void**)&S, g_S);     cudaGetSymbolAddress((void**)&PART, g_PART);
    cudaGetSymbolAddress((void**)&Ahi, g_Ahi); cudaGetSymbolAddress((void**)&Alo, g_Alo);
    cudaGetSymbolAddress((void**)&A1hi, g_A1hi); cudaGetSymbolAddress((void**)&A1lo, g_A1lo);
    cudaGetSymbolAddress((void**)&Dhi, g_Dhi); cudaGetSymbolAddress((void**)&Dlo, g_Dlo);
    cudaGetSymbolAddress((void**)&Qhi, g_Qhi); cudaGetSymbolAddress((void**)&Qlo, g_Qlo);
    cudaGetSymbolAddress((void**)&KVhi, g_KVhi); cudaGetSymbolAddress((void**)&KVlo, g_KVlo);
    cudaGetSymbolAddress((void**)&VThi, g_VThi); cudaGetSymbolAddress((void**)&VTlo, g_VTlo);
    cudaGetSymbolAddress((void**)&Phi, g_Phi); cudaGetSymbolAddress((void**)&Plo, g_Plo);
    cudaGetSymbolAddress((void**)&CThi, g_CThi); cudaGetSymbolAddress((void**)&CTlo, g_CTlo);
    cudaGetSymbolAddress((void**)&MIDhi, g_MIDhi); cudaGetSymbolAddress((void**)&MIDlo, g_MIDlo);
    cudaGetSymbolAddress((void**)&IPWhi, g_IPWhi); cudaGetSymbolAddress((void**)&IPWlo, g_IPWlo);
    cudaGetSymbolAddress((void**)&OWhi, g_OWhi); cudaGetSymbolAddress((void**)&OWlo, g_OWlo);
    cudaGetSymbolAddress((void**)&W1hi, g_W1hi); cudaGetSymbolAddress((void**)&W1lo, g_W1lo);
    cudaGetSymbolAddress((void**)&W2hi, g_W2hi); cudaGetSymbolAddress((void**)&W2lo, g_W2lo);

    const int SMEM128 = 2 * (2*128*40 + 2*128*40) * 2;   // 81920 B
    const int SMEM64  = 2 * (2*128*40 + 2*64*40)  * 2;   // 61440 B
    static int attr_done = 0;
    if (!attr_done) {
        cudaFuncSetAttribute(gemm_bf3<128>, cudaFuncAttributeMaxDynamicSharedMemorySize, SMEM128);
        cudaFuncSetAttribute(gemm_bf3<64>,  cudaFuncAttributeMaxDynamicSharedMemorySize, SMEM64);
        attr_done = 1;
    }

    // ---- prologue: 3 split launches ----
    int q0 = LNUM*3*EDIM*EDIM/4;
    int q1 = q0 + LNUM*EDIM*EDIM/4;
    int q2 = q1 + LNUM*FDIM*EDIM/4;
    int q3 = q2 + LNUM*EDIM*FDIM/4;
    split_weights<<<(q3+255)/256, 256>>>(
        (const float4*)ipw, (const float4*)ow, (const float4*)W1, (const float4*)W2,
        (uint2*)IPWhi, (uint2*)IPWlo, (uint2*)OWhi, (uint2*)OWlo,
        (uint2*)W1hi, (uint2*)W1lo, (uint2*)W2hi, (uint2*)W2lo, q0, q1, q2, q3);
    split_f4<<<(BDIM*SBK*EDIM/4+255)/256, 256>>>((const float4*)dsc, (uint2*)Dhi, (uint2*)Dlo, BDIM*SBK*EDIM/4);
    split_copy<<<(MROWS*EDIM/4+255)/256, 256>>>((const float4*)enc, (uint2*)Ahi, (uint2*)Alo, (float4*)A, MROWS*EDIM/4);

    const long KVSTRIDE = (long)MROWS * 2 * EDIM;
    const long VTSTRIDE = (long)EDIM * MROWS;

    // ---- hoisted: ALL layers' K|V projections as one dense batched GEMM ----
    {
        dim3 gKVall(2*EDIM/128, MROWS/128, LNUM);
        gemm_bf3<128><<<gKVall, 256, SMEM128>>>(
            Dhi, Dlo, IPWhi + EDIM*EDIM, IPWlo + EDIM*EDIM, ipb + EDIM,
            0, KVhi, KVlo,
            EDIM, EDIM, EDIM, 2*EDIM,
            0, 0,
            (long)3*EDIM*EDIM, 0,
            KVSTRIDE, 0, 1,
            (long)3*EDIM,
            1.0f, 1, 0);
        dim3 gTall(EDIM/32, MROWS/32, LNUM);
        dim3 bT(32, 8, 1);
        transpose_v<<<gTall, bT>>>(KVhi, KVlo, VThi, VTlo);
    }

    const float scaleS = 0.125f;   // 1/sqrt(64)
    dim3 gP (EDIM/128, MROWS/128, 1);
    dim3 gF1(FDIM/128, MROWS/128, 1);
    dim3 gS (SBK/128, SAQ/128, BDIM*HNUM);
    dim3 gC (1, SAQ/128, BDIM*HNUM);

    for (int l = 0; l < LNUM; l++) {
        const bf16 *wqh = IPWhi + (long)l*3*EDIM*EDIM, *wql = IPWlo + (long)l*3*EDIM*EDIM;
        const float *bq = ipb + (long)l*3*EDIM;
        const bf16 *KVl_h = KVhi + l*KVSTRIDE, *KVl_l = KVlo + l*KVSTRIDE;
        const bf16 *VTl_h = VThi + l*VTSTRIDE, *VTl_l = VTlo + l*VTSTRIDE;

        // Q = A @ wq^T + bq
        gemm_bf3<128><<<gP, 256, SMEM128>>>(Ahi, Alo, wqh, wql, bq, 0, Qhi, Qlo,
            EDIM, EDIM, EDIM, EDIM, 0,0,0,0,0,0,1, 0, 1.0f, 1, 0);

        // scores = scale * Q @ K^T   (K = KV cols 0..1023, row stride 2048)
        gemm_bf3<128><<<gS, 256, SMEM128>>>(Qhi, Qlo, KVl_h, KVl_l, 0, S, 0, 0,
            DHEAD, EDIM, 2*EDIM, SBK,
            (long)SAQ*EDIM, DHEAD, (long)SBK*2*EDIM, DHEAD,
            (long)HNUM*SAQ*SBK, (long)SAQ*SBK, HNUM, 0, scaleS, 0, 0);

        softmax512<<<BDIM*HNUM*SAQ/8, 256>>>(S, Phi, Plo);

        // ctx = P @ V  (TN vs VT)
        gemm_bf3<64><<<gC, 256, SMEM64>>>(Phi, Plo, VTl_h, VTl_l, 0, 0, CThi, CTlo,
            SBK, SBK, MROWS, EDIM,
            (long)HNUM*SAQ*SBK, (long)SAQ*SBK,
            (long)SBK, (long)DHEAD*MROWS,
            (long)SAQ*EDIM, DHEAD, HNUM, 0, 1.0f, 1, 0);

        gemm_bf3<128><<<gP, 256, SMEM128>>>(CThi, CTlo, OWhi + (long)l*EDIM*EDIM,
            OWlo + (long)l*EDIM*EDIM, ob + (long)l*EDIM, TMP, 0, 0,
            EDIM, EDIM, EDIM, EDIM, 0,0,0,0,0,0,1, 0, 1.0f, 0, 0);

        add_ln<<<MROWS, 256>>>(A, TMP, g1 + (long)l*EDIM, b1 + (long)l*EDIM,
                               A1, A1hi, A1lo);

        gemm_bf3<128><<<gF1, 256, SMEM128>>>(A1hi, A1lo, W1hi + (long)l*FDIM*EDIM,
            W1lo + (long)l*FDIM*EDIM, bb1 + (long)l*FDIM, 0, MIDhi, MIDlo,
            EDIM, EDIM, EDIM, FDIM, 0,0,0,0,0,0,1, 0, 1.0f, 1, 1);

        gemm_bf3<128><<<gP, 256, SMEM128>>>(MIDhi, MIDlo, W2hi + (long)l*EDIM*FDIM,
            W2lo + (long)l*EDIM*FDIM, bb2 + (long)l*EDIM, TMP, 0, 0,
            FDIM, FDIM, FDIM, EDIM, 0,0,0,0,0,0,1, 0, 1.0f, 0, 0);

        add_ln<<<MROWS, 256>>>(A1, TMP, g2 + (long)l*EDIM, b2 + (long)l*EDIM,
                               A, Ahi, Alo);
    }

    classify<<<MROWS/8, 256>>>(A, cw, cb, labels, maskA, cand, (float*)d_out, PART);
    finalize<<<1, 512>>>(PART, (float*)d_out);
}